// round 9
// baseline (speedup 1.0000x reference)
#include <cuda_runtime.h>

// Problem constants
#define B_   4
#define N_   2048
#define FIN  256
#define H_   4
#define FO_  64
#define HF   256               // H_*FO_
#define M_   (B_*N_)           // 8192 rows of h
#define NH   (M_*H_)           // 32768 (node, head) pairs

// Scratch (device globals — no allocation allowed)
__device__ float g_h[M_ * HF];                      // h = x@W, 8 MB
__device__ float g_s[NH], g_dv[NH];
__device__ float g_A1[NH], g_A2[NH], g_E1[NH], g_E2[NH];

// ---------------- packed f32x2 helpers (Blackwell FFMA2) ----------------
__device__ __forceinline__ unsigned long long dup2(float x) {
    unsigned long long d;
    unsigned int u = __float_as_uint(x);
    asm("mov.b64 %0, {%1, %1};" : "=l"(d) : "r"(u));
    return d;
}
__device__ __forceinline__ void fma2(unsigned long long& acc,
                                     unsigned long long a, unsigned long long b) {
    asm("fma.rn.f32x2 %0, %1, %2, %0;" : "+l"(acc) : "l"(a), "l"(b));
}
__device__ __forceinline__ float2 unp2(unsigned long long v) {
    float2 r;
    asm("mov.b64 {%0, %1}, %2;" : "=f"(r.x), "=f"(r.y) : "l"(v));
    return r;
}

// ---------------- Kernel 1: h = x @ W  (8192x256 @ 256x256) ----------------
// 128x64 block tile, 128 threads, 8x8 microtile, BK=16.  (R6 version)
__global__ __launch_bounds__(128) void gemm_kernel(const float* __restrict__ x,
                                                   const float* __restrict__ W) {
    __shared__ float As[16][132];   // As[k][m], padded
    __shared__ float Bs[16][68];    // Bs[k][n], padded

    const int t  = threadIdx.x;
    const int m0 = blockIdx.x * 128;
    const int n0 = blockIdx.y * 64;
    const int gm = t >> 3;          // 0..15 -> rows gm*8..+7
    const int gn = t & 7;           // 0..7  -> cols gn*8..+7

    float acc[8][8];
#pragma unroll
    for (int i = 0; i < 8; i++)
#pragma unroll
        for (int j = 0; j < 8; j++) acc[i][j] = 0.f;

    for (int k0 = 0; k0 < FIN; k0 += 16) {
        float4 xv[4];
        const float* xrow = x + (size_t)(m0 + t) * FIN + k0;
#pragma unroll
        for (int q = 0; q < 4; q++) xv[q] = *(const float4*)(xrow + 4 * q);

        float4 wv0, wv1;
        {
            const int kr = t >> 3;
            const int cp = (t & 7) * 8;
            const float* wrow = W + (size_t)(k0 + kr) * HF + n0 + cp;
            wv0 = *(const float4*)(wrow);
            wv1 = *(const float4*)(wrow + 4);
        }

        __syncthreads();
#pragma unroll
        for (int q = 0; q < 4; q++) {
            As[4 * q + 0][t] = xv[q].x;
            As[4 * q + 1][t] = xv[q].y;
            As[4 * q + 2][t] = xv[q].z;
            As[4 * q + 3][t] = xv[q].w;
        }
        {
            const int kr = t >> 3;
            const int cp = (t & 7) * 8;
            *(float4*)&Bs[kr][cp]     = wv0;
            *(float4*)&Bs[kr][cp + 4] = wv1;
        }
        __syncthreads();

#pragma unroll
        for (int kk = 0; kk < 16; kk++) {
            float a[8], b[8];
            *(float4*)(a)     = *(const float4*)&As[kk][gm * 8];
            *(float4*)(a + 4) = *(const float4*)&As[kk][gm * 8 + 4];
            *(float4*)(b)     = *(const float4*)&Bs[kk][gn * 8];
            *(float4*)(b + 4) = *(const float4*)&Bs[kk][gn * 8 + 4];
#pragma unroll
            for (int i = 0; i < 8; i++)
#pragma unroll
                for (int j = 0; j < 8; j++) acc[i][j] += a[i] * b[j];
        }
    }

#pragma unroll
    for (int i = 0; i < 8; i++) {
        float* orow = g_h + (size_t)(m0 + gm * 8 + i) * HF + n0 + gn * 8;
        *(float4*)(orow)     = make_float4(acc[i][0], acc[i][1], acc[i][2], acc[i][3]);
        *(float4*)(orow + 4) = make_float4(acc[i][4], acc[i][5], acc[i][6], acc[i][7]);
    }
}

// ---------------- Kernel 2: attention coefficients + exp factors ----------------
__global__ __launch_bounds__(256) void attn_coef_kernel(const float* __restrict__ a_src,
                                                        const float* __restrict__ a_dst) {
    const int nh   = (blockIdx.x * blockDim.x + threadIdx.x) >> 5;
    const int lane = threadIdx.x & 31;
    if (nh >= NH) return;
    const int head = nh & (H_ - 1);

    const float* hrow = g_h + (size_t)nh * FO_;
    const float v0 = hrow[lane];
    const float v1 = hrow[lane + 32];
    const float* as = a_src + head * FO_;
    const float* ad = a_dst + head * FO_;
    float ps = v0 * as[lane] + v1 * as[lane + 32];
    float pd = v0 * ad[lane] + v1 * ad[lane + 32];
#pragma unroll
    for (int o = 16; o > 0; o >>= 1) {
        ps += __shfl_xor_sync(0xffffffffu, ps, o);
        pd += __shfl_xor_sync(0xffffffffu, pd, o);
    }
    if (lane == 0) {
        g_s[nh]  = ps;
        g_A1[nh] = expf(ps);
        g_A2[nh] = expf(0.2f * ps);
        g_dv[nh] = pd;
        g_E1[nh] = expf(pd);
        g_E2[nh] = expf(0.2f * pd);
    }
}

// ---------------- Kernel 3: masked-softmax attention + P@V ----------------
// TI=64, 128 threads, 4i x 8f microtile -> ~32 acc regs, high occupancy
// (single wave, ~3.5 warps/SMSP to keep the FFMA2 pipe fed through
// Phase B / barrier bubbles of co-resident CTAs).
// Phase B: thread t owns row (t&63), jj half (t>>7? no: t>>6); denominator
// combined from the two halves via smem partials (no atomics).
#define TI 64
#define TJ 32

__global__ __launch_bounds__(128, 5) void gat_attn_kernel(const float* __restrict__ adj,
                                                          float* __restrict__ out) {
    __shared__ __align__(16) float h_s[TJ][68];     // natural (f,f+1) pairs
    __shared__ __align__(16) float w_s[TJ][TI];     // weights, natural
    __shared__ __align__(16) float4 de_s[TJ];       // {d, E1, E2, 0}
    __shared__ float dpart[2][TI];

    const int t    = threadIdx.x;
    const int ib   = blockIdx.x;    // 0..31
    const int head = blockIdx.y;    // 0..3
    const int b    = blockIdx.z;    // 0..3

    // ---- Phase B identity: row within tile + jj half ----
    const int row  = t & 63;
    const int half = t >> 6;        // 0/1 -> jj in [half*16, half*16+16)
    const int i_g  = ib * TI + row;
    const int nh_i = (b * N_ + i_g) * H_ + head;
    const float s_i = g_s[nh_i];
    const float A1  = g_A1[nh_i];
    const float A2  = g_A2[nh_i];
    float denom = 0.f;

    // ---- Phase C identity: 4i x 8f microtile ----
    const int g = t >> 3;     // i-group 0..15 -> rows g*4..g*4+3
    const int c = t & 7;      // f-chunk 0..7

    unsigned long long acc[4][4];
#pragma unroll
    for (int i = 0; i < 4; i++)
#pragma unroll
        for (int fp = 0; fp < 4; fp++) acc[i][fp] = 0ull;

    const float* adjbase = adj + (size_t)i_g * N_ + half * 16;

    // h-tile loader mapping: row jr (0..31), 16 floats at col 'part'
    const int jr   = t >> 2;
    const int part = (t & 3) * 16;

    // prologue: prefetch tile 0 into registers
    float4 hreg[4];
    float nd = 0.f, ne1 = 0.f, ne2 = 0.f;
    {
        const float* hrow = g_h + ((size_t)((b * N_ + jr) * H_ + head)) * FO_ + part;
#pragma unroll
        for (int q = 0; q < 4; q++) hreg[q] = *(const float4*)(hrow + 4 * q);
        if (t < TJ) {
            const int nh_j = (b * N_ + t) * H_ + head;
            nd = g_dv[nh_j]; ne1 = g_E1[nh_j]; ne2 = g_E2[nh_j];
        }
    }

    for (int jt = 0; jt < N_ / TJ; jt++) {
        // adj loads for this tile (16 values for this thread's half)
        float4 av[4];
        const float* arow = adjbase + jt * TJ;
#pragma unroll
        for (int q = 0; q < 4; q++) av[q] = *(const float4*)(arow + 4 * q);

        __syncthreads();   // previous FMA phase done reading smem
#pragma unroll
        for (int q = 0; q < 4; q++) *(float4*)&h_s[jr][part + 4 * q] = hreg[q];
        if (t < TJ) de_s[t] = make_float4(nd, ne1, ne2, 0.f);
        __syncthreads();

        // prefetch next tile (hidden under phase B + C)
        if (jt + 1 < N_ / TJ) {
            const int j0 = (jt + 1) * TJ;
            const float* hrow = g_h + ((size_t)((b * N_ + j0 + jr) * H_ + head)) * FO_ + part;
#pragma unroll
            for (int q = 0; q < 4; q++) hreg[q] = *(const float4*)(hrow + 4 * q);
            if (t < TJ) {
                const int nh_j = (b * N_ + j0 + t) * H_ + head;
                nd = g_dv[nh_j]; ne1 = g_E1[nh_j]; ne2 = g_E2[nh_j];
            }
        }

        // ---- Phase B: factored softmax weights (no exp), 16 jj per thread ----
        const float* afl = (const float*)av;
#pragma unroll
        for (int jje = 0; jje < 16; jje++) {
            const int jj    = half * 16 + jje;
            const float a   = afl[jje];
            const float4 de = de_s[jj];
            const float t0  = s_i + de.x;
            float w = (t0 > 0.f) ? (A1 * de.y) : (A2 * de.z);
            w = (a != 0.f) ? w : 0.f;
            denom += w;
            w_s[jj][row] = w;
        }
        __syncthreads();

        // ---- Phase C: out_tile += w * h, packed f32x2 ----
#pragma unroll 4
        for (int jj = 0; jj < TJ; jj++) {
            const float4 w0 = *(const float4*)&w_s[jj][g * 4];
            unsigned long long wd[4];
            wd[0] = dup2(w0.x); wd[1] = dup2(w0.y);
            wd[2] = dup2(w0.z); wd[3] = dup2(w0.w);

            unsigned long long hp[4];
            {
                const ulonglong2 v0 = *(const ulonglong2*)&h_s[jj][c * 8];
                const ulonglong2 v1 = *(const ulonglong2*)&h_s[jj][c * 8 + 4];
                hp[0] = v0.x; hp[1] = v0.y; hp[2] = v1.x; hp[3] = v1.y;
            }
#pragma unroll
            for (int i = 0; i < 4; i++)
#pragma unroll
                for (int fp = 0; fp < 4; fp++) fma2(acc[i][fp], wd[i], hp[fp]);
        }
    }

    dpart[half][row] = denom;
    __syncthreads();

    // store (f-contiguous float4 pairs per i-row)
#pragma unroll
    for (int i = 0; i < 4; i++) {
        const int rl   = g * 4 + i;
        const float r  = 1.0f / (dpart[0][rl] + dpart[1][rl]);
        const int grow = b * N_ + ib * TI + rl;
        float* orow    = out + (size_t)grow * HF + head * FO_ + c * 8;
        const float2 p0 = unp2(acc[i][0]);
        const float2 p1 = unp2(acc[i][1]);
        const float2 p2 = unp2(acc[i][2]);
        const float2 p3 = unp2(acc[i][3]);
        *(float4*)(orow)     = make_float4(p0.x * r, p0.y * r, p1.x * r, p1.y * r);
        *(float4*)(orow + 4) = make_float4(p2.x * r, p2.y * r, p3.x * r, p3.y * r);
    }
}

// ---------------- launch ----------------
extern "C" void kernel_launch(void* const* d_in, const int* in_sizes, int n_in,
                              void* d_out, int out_size) {
    (void)in_sizes; (void)n_in; (void)out_size;
    const float* x     = (const float*)d_in[0];
    const float* adj   = (const float*)d_in[1];
    const float* W     = (const float*)d_in[2];
    const float* a_src = (const float*)d_in[3];
    const float* a_dst = (const float*)d_in[4];
    float* out = (float*)d_out;

    gemm_kernel<<<dim3(M_ / 128, HF / 64), 128>>>(x, W);
    attn_coef_kernel<<<(NH * 32) / 256, 256>>>(a_src, a_dst);
    gat_attn_kernel<<<dim3(N_ / TI, H_, B_), 128>>>(adj, out);
}

// round 11
// speedup vs baseline: 2.7270x; 2.7270x over previous
#include <cuda_runtime.h>
#include <cstdint>

// Problem constants
#define B_   4
#define N_   2048
#define FIN  256
#define H_   4
#define FO_  64
#define HF   256               // H_*FO_
#define M_   (B_*N_)           // 8192 rows of h
#define NH   (M_*H_)           // 32768 (node, head) pairs

// Scratch (device globals — no allocation allowed)
__device__ float g_h [M_ * HF];                 // h = x@W exact fp32 (coef kernel)
__device__ float g_hr[M_ * HF];                 // h tf32-rounded (attention B operand)
__device__ float g_s[NH], g_dv[NH];
__device__ float g_A1[NH], g_A2[NH], g_E1[NH], g_E2[NH];

// ---------------- helpers ----------------
__device__ __forceinline__ float tf32r(float x) {   // round-to-nearest tf32 (sm_80+ baseline)
    float r; asm("cvt.rna.tf32.f32 %0, %1;" : "=f"(r) : "f"(x)); return r;
}
// m16n8k8 tf32 mma (sm_80+ baseline PTX, no 'a' target needed)
__device__ __forceinline__ void mma8(float* d,
                                     uint32_t a0, uint32_t a1, uint32_t a2, uint32_t a3,
                                     uint32_t b0, uint32_t b1) {
    asm volatile(
        "mma.sync.aligned.m16n8k8.row.col.f32.tf32.tf32.f32 "
        "{%0,%1,%2,%3}, {%4,%5,%6,%7}, {%8,%9}, {%0,%1,%2,%3};"
        : "+f"(d[0]), "+f"(d[1]), "+f"(d[2]), "+f"(d[3])
        : "r"(a0), "r"(a1), "r"(a2), "r"(a3), "r"(b0), "r"(b1));
}
__device__ __forceinline__ uint32_t fbits(float x) { return __float_as_uint(x); }

// ---------------- Kernel 1: h = x @ W  (+ tf32-rounded copy) ----------------
__global__ __launch_bounds__(128) void gemm_kernel(const float* __restrict__ x,
                                                   const float* __restrict__ W) {
    __shared__ float As[16][132];
    __shared__ float Bs[16][68];

    const int t  = threadIdx.x;
    const int m0 = blockIdx.x * 128;
    const int n0 = blockIdx.y * 64;
    const int gm = t >> 3;
    const int gn = t & 7;

    float acc[8][8];
#pragma unroll
    for (int i = 0; i < 8; i++)
#pragma unroll
        for (int j = 0; j < 8; j++) acc[i][j] = 0.f;

    for (int k0 = 0; k0 < FIN; k0 += 16) {
        float4 xv[4];
        const float* xrow = x + (size_t)(m0 + t) * FIN + k0;
#pragma unroll
        for (int q = 0; q < 4; q++) xv[q] = *(const float4*)(xrow + 4 * q);

        float4 wv0, wv1;
        {
            const int kr = t >> 3;
            const int cp = (t & 7) * 8;
            const float* wrow = W + (size_t)(k0 + kr) * HF + n0 + cp;
            wv0 = *(const float4*)(wrow);
            wv1 = *(const float4*)(wrow + 4);
        }

        __syncthreads();
#pragma unroll
        for (int q = 0; q < 4; q++) {
            As[4 * q + 0][t] = xv[q].x;
            As[4 * q + 1][t] = xv[q].y;
            As[4 * q + 2][t] = xv[q].z;
            As[4 * q + 3][t] = xv[q].w;
        }
        {
            const int kr = t >> 3;
            const int cp = (t & 7) * 8;
            *(float4*)&Bs[kr][cp]     = wv0;
            *(float4*)&Bs[kr][cp + 4] = wv1;
        }
        __syncthreads();

#pragma unroll
        for (int kk = 0; kk < 16; kk++) {
            float a[8], b[8];
            *(float4*)(a)     = *(const float4*)&As[kk][gm * 8];
            *(float4*)(a + 4) = *(const float4*)&As[kk][gm * 8 + 4];
            *(float4*)(b)     = *(const float4*)&Bs[kk][gn * 8];
            *(float4*)(b + 4) = *(const float4*)&Bs[kk][gn * 8 + 4];
#pragma unroll
            for (int i = 0; i < 8; i++)
#pragma unroll
                for (int j = 0; j < 8; j++) acc[i][j] += a[i] * b[j];
        }
    }

#pragma unroll
    for (int i = 0; i < 8; i++) {
        const size_t off = (size_t)(m0 + gm * 8 + i) * HF + n0 + gn * 8;
        float* orow = g_h + off;
        *(float4*)(orow)     = make_float4(acc[i][0], acc[i][1], acc[i][2], acc[i][3]);
        *(float4*)(orow + 4) = make_float4(acc[i][4], acc[i][5], acc[i][6], acc[i][7]);
        float* rrow = g_hr + off;
        *(float4*)(rrow)     = make_float4(tf32r(acc[i][0]), tf32r(acc[i][1]),
                                           tf32r(acc[i][2]), tf32r(acc[i][3]));
        *(float4*)(rrow + 4) = make_float4(tf32r(acc[i][4]), tf32r(acc[i][5]),
                                           tf32r(acc[i][6]), tf32r(acc[i][7]));
    }
}

// ---------------- Kernel 2: attention coefficients + exp factors ----------------
__global__ __launch_bounds__(256) void attn_coef_kernel(const float* __restrict__ a_src,
                                                        const float* __restrict__ a_dst) {
    const int nh   = (blockIdx.x * blockDim.x + threadIdx.x) >> 5;
    const int lane = threadIdx.x & 31;
    if (nh >= NH) return;
    const int head = nh & (H_ - 1);

    const float* hrow = g_h + (size_t)nh * FO_;
    const float v0 = hrow[lane];
    const float v1 = hrow[lane + 32];
    const float* as = a_src + head * FO_;
    const float* ad = a_dst + head * FO_;
    float ps = v0 * as[lane] + v1 * as[lane + 32];
    float pd = v0 * ad[lane] + v1 * ad[lane + 32];
#pragma unroll
    for (int o = 16; o > 0; o >>= 1) {
        ps += __shfl_xor_sync(0xffffffffu, ps, o);
        pd += __shfl_xor_sync(0xffffffffu, pd, o);
    }
    if (lane == 0) {
        g_s[nh]  = ps;
        g_A1[nh] = expf(ps);
        g_A2[nh] = expf(0.2f * ps);
        g_dv[nh] = pd;
        g_E1[nh] = expf(pd);
        g_E2[nh] = expf(0.2f * pd);
    }
}

// ---------------- Kernel 3: mma.sync tf32 attention ----------------
// Block = (i-block 128, head, b), 128 threads = 4 warps; warp wi owns rows wi*32..+31.
// Per j-tile of 32 (k=32 -> 4 mma k-steps):
//   k-permutation j(kappa) = (kappa&3)*8 + (kappa>>2): thread (g,c) computes its
//   A-fragment weights (4 rows x 8 contiguous j) straight into registers.
//   h-tile has a 65th column of ones -> D col 64 = per-row denominator, computed
//   by the SAME mma chain as the numerator (exact consistency).
#define TJ  32
#define HSW 73     // h_s row width: 72 used cols + pad -> B-frag LDS conflict-free

__global__ __launch_bounds__(128) void gat_attn_mma(const float* __restrict__ adj,
                                                    float* __restrict__ out) {
    __shared__ __align__(16) float adj_s[128][36];
    __shared__ float h_s[TJ][HSW];
    __shared__ __align__(16) float4 de_s[TJ];
    __shared__ float den_s[4][32];

    const int t    = threadIdx.x;
    const int wi   = t >> 5;
    const int lane = t & 31;
    const int g    = lane >> 2;    // groupID 0..7
    const int c    = lane & 3;     // threadID_in_group 0..3
    const int ib   = blockIdx.x;
    const int head = blockIdx.y;
    const int b    = blockIdx.z;

    // per-thread row coefficients: rr = mt*2 + hi -> row wi*32 + mt*16 + hi*8 + g
    float si[4], A1[4], A2[4];
#pragma unroll
    for (int rr = 0; rr < 4; rr++) {
        const int row = ib * 128 + wi * 32 + (rr >> 1) * 16 + (rr & 1) * 8 + g;
        const int nh  = (b * N_ + row) * H_ + head;
        si[rr] = g_s[nh]; A1[rr] = g_A1[nh]; A2[rr] = g_A2[nh];
    }

    float D[2][9][4];
#pragma unroll
    for (int mt = 0; mt < 2; mt++)
#pragma unroll
        for (int nt = 0; nt < 9; nt++)
#pragma unroll
            for (int q = 0; q < 4; q++) D[mt][nt][q] = 0.f;

    // ones/zero pad columns of h_s (written once; staging only touches cols 0..63)
    if (t < TJ) {
        h_s[t][64] = 1.0f;
#pragma unroll
        for (int k = 65; k < HSW; k++) h_s[t][k] = 0.0f;
    }

    const float* adjtile = adj + (size_t)(ib * 128) * N_;
    const float* hbase   = g_hr + (size_t)(b * N_) * HF + head * FO_;

    // staging mappings
    const int xr = t >> 3;          // adj row helper (rows xr + k*16)
    const int xc = (t & 7) * 4;     // adj col (float4)
    const int jr = t >> 2;          // h row 0..31
    const int jc = (t & 3) * 16;    // h col group

    // prologue: prefetch tile 0
    float4 aj[8]; float4 hb[4];
    float nd = 0.f, ne1 = 0.f, ne2 = 0.f;
    {
#pragma unroll
        for (int k = 0; k < 8; k++)
            aj[k] = *(const float4*)(adjtile + (size_t)(xr + k * 16) * N_ + xc);
#pragma unroll
        for (int q = 0; q < 4; q++)
            hb[q] = *(const float4*)(hbase + (size_t)jr * HF + jc + 4 * q);
        if (t < TJ) {
            const int nh_j = (b * N_ + t) * H_ + head;
            nd = g_dv[nh_j]; ne1 = g_E1[nh_j]; ne2 = g_E2[nh_j];
        }
    }

    for (int jt = 0; jt < N_ / TJ; jt++) {
        __syncthreads();   // previous tile's Phase B / mma done reading smem
#pragma unroll
        for (int k = 0; k < 8; k++)
            *(float4*)&adj_s[xr + k * 16][xc] = aj[k];
#pragma unroll
        for (int q = 0; q < 4; q++) {
            h_s[jr][jc + 4 * q + 0] = ((const float*)&hb[q])[0];
            h_s[jr][jc + 4 * q + 1] = ((const float*)&hb[q])[1];
            h_s[jr][jc + 4 * q + 2] = ((const float*)&hb[q])[2];
            h_s[jr][jc + 4 * q + 3] = ((const float*)&hb[q])[3];
        }
        if (t < TJ) de_s[t] = make_float4(nd, ne1, ne2, 0.f);
        __syncthreads();

        // prefetch next tile (LDG latency hidden under Phase B + mma)
        if (jt + 1 < N_ / TJ) {
            const int j0 = (jt + 1) * TJ;
#pragma unroll
            for (int k = 0; k < 8; k++)
                aj[k] = *(const float4*)(adjtile + (size_t)(xr + k * 16) * N_ + j0 + xc);
#pragma unroll
            for (int q = 0; q < 4; q++)
                hb[q] = *(const float4*)(hbase + (size_t)(j0 + jr) * HF + jc + 4 * q);
            if (t < TJ) {
                const int nh_j = (b * N_ + j0 + t) * H_ + head;
                nd = g_dv[nh_j]; ne1 = g_E1[nh_j]; ne2 = g_E2[nh_j];
            }
        }

        // ---- Phase B: factored weights straight into A-fragment registers ----
        // thread's j set: j = c*8 + u, u = 0..7 (contiguous)
        float4 der[8];
#pragma unroll
        for (int u = 0; u < 8; u++) der[u] = de_s[c * 8 + u];

        float wv[4][8];
#pragma unroll
        for (int rr = 0; rr < 4; rr++) {
            const int rl = wi * 32 + (rr >> 1) * 16 + (rr & 1) * 8 + g;
            float av[8];
            *(float4*)(av)     = *(const float4*)&adj_s[rl][c * 8];
            *(float4*)(av + 4) = *(const float4*)&adj_s[rl][c * 8 + 4];
#pragma unroll
            for (int u = 0; u < 8; u++) {
                const float t0 = si[rr] + der[u].x;
                float w = (t0 > 0.f) ? (A1[rr] * der[u].y) : (A2[rr] * der[u].z);
                w = (av[u] != 0.f) ? w : 0.f;
                wv[rr][u] = tf32r(w);
            }
        }

        // ---- mma phase: D += W * H (k-permuted; both sides use j(kappa)) ----
#pragma unroll
        for (int s = 0; s < 4; s++) {
            const uint32_t a00 = fbits(wv[0][2 * s]);
            const uint32_t a01 = fbits(wv[1][2 * s]);
            const uint32_t a02 = fbits(wv[0][2 * s + 1]);
            const uint32_t a03 = fbits(wv[1][2 * s + 1]);
            const uint32_t a10 = fbits(wv[2][2 * s]);
            const uint32_t a11 = fbits(wv[3][2 * s]);
            const uint32_t a12 = fbits(wv[2][2 * s + 1]);
            const uint32_t a13 = fbits(wv[3][2 * s + 1]);
            const float* hr0 = &h_s[c * 8 + 2 * s][g];       // b0 j-row
            const float* hr1 = &h_s[c * 8 + 2 * s + 1][g];   // b1 j-row
#pragma unroll
            for (int nt = 0; nt < 9; nt++) {
                const uint32_t b0 = fbits(hr0[nt * 8]);
                const uint32_t b1 = fbits(hr1[nt * 8]);
                mma8(D[0][nt], a00, a01, a02, a03, b0, b1);
                mma8(D[1][nt], a10, a11, a12, a13, b0, b1);
            }
        }
    }

    // ---- epilogue: denominators live in D col 64 (nt=8, c==0 threads) ----
    if (c == 0) {
        den_s[wi][g]      = D[0][8][0];
        den_s[wi][g + 8]  = D[0][8][2];
        den_s[wi][16 + g] = D[1][8][0];
        den_s[wi][24 + g] = D[1][8][2];
    }
    __syncwarp();

#pragma unroll
    for (int mt = 0; mt < 2; mt++)
#pragma unroll
        for (int hi = 0; hi < 2; hi++) {
            const int rl   = mt * 16 + hi * 8 + g;
            const float r  = 1.0f / den_s[wi][rl];
            const int grow = b * N_ + ib * 128 + wi * 32 + rl;
            float* orow    = out + (size_t)grow * HF + head * FO_;
#pragma unroll
            for (int nt = 0; nt < 8; nt++) {
                float2 v;
                v.x = D[mt][nt][hi * 2]     * r;
                v.y = D[mt][nt][hi * 2 + 1] * r;
                *(float2*)(orow + nt * 8 + 2 * c) = v;
            }
        }
}

// ---------------- launch ----------------
extern "C" void kernel_launch(void* const* d_in, const int* in_sizes, int n_in,
                              void* d_out, int out_size) {
    (void)in_sizes; (void)n_in; (void)out_size;
    const float* x     = (const float*)d_in[0];
    const float* adj   = (const float*)d_in[1];
    const float* W     = (const float*)d_in[2];
    const float* a_src = (const float*)d_in[3];
    const float* a_dst = (const float*)d_in[4];
    float* out = (float*)d_out;

    gemm_kernel<<<dim3(M_ / 128, HF / 64), 128>>>(x, W);
    attn_coef_kernel<<<(NH * 32) / 256, 256>>>(a_src, a_dst);
    gat_attn_mma<<<dim3(N_ / 128, H_, B_), 128>>>(adj, out);
}